// round 1
// baseline (speedup 1.0000x reference)
#include <cuda_runtime.h>

#define FF_   481
#define KK_   48
#define TT_   1024
#define BB_   4
#define CHF_  1924          // 4*481
#define TILE_ 32
#define NTH_  192

__global__ __launch_bounds__(NTH_, 2)
void pv_main_kernel(const float* __restrict__ bins_re,
                    const float* __restrict__ bins_im,
                    const float* __restrict__ band_re,
                    const float* __restrict__ band_im,
                    const float* __restrict__ c2pv_re,
                    const float* __restrict__ c2pv_im,
                    float* __restrict__ out)
{
    extern __shared__ float smem[];
    float2* adj  = (float2*)smem;            // 481*16 float2
    float2* bcs  = adj + FF_ * 16;           // 48*16 float2
    float*  xs   = (float*)(bcs + KK_ * 16); // 2*1924 floats (re then im)
    float*  btr  = xs + 2 * CHF_;            // TILE*48
    float*  bti  = btr + TILE_ * KK_;        // TILE*48
    float*  c2r  = bti + TILE_ * KK_;        // 256
    float*  c2i  = c2r + 256;                // 256
    float*  invds = c2i + 256;               // 48

    const int tid = threadIdx.x;
    const int t   = blockIdx.x;
    const int b   = blockIdx.y;
    const size_t base = (size_t)(b * TT_ + t) * CHF_;

    // cooperative load of this (b,t)'s 4-channel spectrum + c2pv matrices
    for (int i = tid; i < CHF_; i += NTH_) {
        xs[i]        = bins_re[base + i];
        xs[CHF_ + i] = bins_im[base + i];
    }
    for (int i = tid; i < 256; i += NTH_) {
        c2r[i] = c2pv_re[i];
        c2i[i] = c2pv_im[i];
    }
    __syncthreads();

    // ---------------- Phase A: phase-adjusted covariance (no trig) ----------
    for (int f = tid; f < FF_; f += NTH_) {
        int fm = f - 1;
        if (fm < 0) fm = 0;
        if (fm > FF_ - 3) fm = FF_ - 3;
        const int fp = fm + 2;

        float xr[4], xi[4], mr[4], mi[4], pr[4], pi2[4];
        #pragma unroll
        for (int ch = 0; ch < 4; ch++) {
            xr[ch]  = xs[ch * FF_ + f];   xi[ch]  = xs[CHF_ + ch * FF_ + f];
            mr[ch]  = xs[ch * FF_ + fm];  mi[ch]  = xs[CHF_ + ch * FF_ + fm];
            pr[ch]  = xs[ch * FF_ + fp];  pi2[ch] = xs[CHF_ + ch * FF_ + fp];
        }
        float d[4];
        #pragma unroll
        for (int ch = 0; ch < 4; ch++) d[ch] = xr[ch]*xr[ch] + xi[ch]*xi[ch];
        const float invp = 1.0f / fmaxf(d[0] + d[1] + d[2] + d[3], 1e-20f);
        #pragma unroll
        for (int ch = 0; ch < 4; ch++)
            adj[f * 16 + 5 * ch] = make_float2(d[ch] * invp, 0.0f);

        const int pu[6] = {0, 0, 0, 1, 1, 2};
        const int pv_[6] = {1, 2, 3, 2, 3, 3};
        #pragma unroll
        for (int u = 0; u < 6; u++) {
            const int i = pu[u], j = pv_[u];
            // cov[i,j] = x_i * conj(x_j)
            float cr  = xr[i]*xr[j]  + xi[i]*xi[j];
            float ci  = xi[i]*xr[j]  - xr[i]*xi[j];
            float amr = mr[i]*mr[j]  + mi[i]*mi[j];
            float ami = mi[i]*mr[j]  - mr[i]*mi[j];
            float apr = pr[i]*pr[j]  + pi2[i]*pi2[j];
            float api = pi2[i]*pr[j] - pr[i]*pi2[j];
            // z = conj(cov[fm]) * cov[fp]  (positive per-f power scaling cancels)
            float zr = amr*apr + ami*api;
            float zi = amr*api - ami*apr;
            float mag = sqrtf(cr*cr + ci*ci) * invp;
            float s   = mag * rsqrtf(fmaxf(zr*zr + zi*zi, 1e-40f));
            float vr = zr * s, vi = zi * s;
            adj[f * 16 + i * 4 + j] = make_float2(vr,  vi);
            adj[f * 16 + j * 4 + i] = make_float2(vr, -vi);  // Hermitian mirror
        }
    }
    __syncthreads();

    // ---------------- Phase B: complex band matmul (F-tiled via smem) -------
    const int k  = tid % KK_;       // 0..47
    const int cg = tid / KK_;       // 0..3
    const int c0 = cg * 4;
    float accr[4] = {0.f, 0.f, 0.f, 0.f};
    float acci[4] = {0.f, 0.f, 0.f, 0.f};

    for (int f0 = 0; f0 < FF_; f0 += TILE_) {
        const int nf = (FF_ - f0 < TILE_) ? (FF_ - f0) : TILE_;
        const int nelem = nf * KK_;
        for (int i = tid; i < nelem; i += NTH_) {
            btr[i] = band_re[f0 * KK_ + i];
            bti[i] = band_im[f0 * KK_ + i];
        }
        __syncthreads();
        for (int ff = 0; ff < nf; ff++) {
            const float br = btr[ff * KK_ + k];
            const float bi = bti[ff * KK_ + k];
            const float4* arow = (const float4*)(adj + (f0 + ff) * 16 + c0);
            const float4 a01 = arow[0];   // (c0.re, c0.im, c1.re, c1.im)
            const float4 a23 = arow[1];
            accr[0] += a01.x * br - a01.y * bi;  acci[0] += a01.x * bi + a01.y * br;
            accr[1] += a01.z * br - a01.w * bi;  acci[1] += a01.z * bi + a01.w * br;
            accr[2] += a23.x * br - a23.y * bi;  acci[2] += a23.x * bi + a23.y * br;
            accr[3] += a23.z * br - a23.w * bi;  acci[3] += a23.z * bi + a23.w * br;
        }
        __syncthreads();
    }
    #pragma unroll
    for (int j = 0; j < 4; j++)
        bcs[k * 16 + c0 + j] = make_float2(accr[j], acci[j]);
    __syncthreads();

    if (tid < KK_) {
        const float dsum = bcs[tid*16 + 0].x + bcs[tid*16 + 5].x +
                           bcs[tid*16 + 10].x + bcs[tid*16 + 15].x;
        invds[tid] = 1.0f / fmaxf(dsum, 1e-20f);
    }
    __syncthreads();

    // ---------------- Projection Re(c2pv @ bc) / ds (IIR commutes; done later)
    const float sc = invds[k];
    float pvv[4] = {0.f, 0.f, 0.f, 0.f};
    #pragma unroll
    for (int c = 0; c < 16; c++) {
        const float2 v = bcs[k * 16 + c];
        #pragma unroll
        for (int j = 0; j < 4; j++) {
            const int p = c0 + j;
            pvv[j] += c2r[p * 16 + c] * v.x - c2i[p * 16 + c] * v.y;
        }
    }
    float4 o;
    o.x = pvv[0] * sc; o.y = pvv[1] * sc; o.z = pvv[2] * sc; o.w = pvv[3] * sc;
    const size_t obase = (((size_t)(b * KK_ + k)) * TT_ + t) * 16 + c0;
    *(float4*)(out + obase) = o;
}

// In-place real-coefficient IIR over frames on d_out (B,K,T,16).
// Real IIR commutes with the real-linear c2pv projection, so smoothing the
// projected values is exact.
__global__ void pv_iir_kernel(float* __restrict__ out, const float* __restrict__ tau)
{
    const int chain = blockIdx.x * blockDim.y + threadIdx.y;  // 0..191 = b*48+k
    const int p = threadIdx.x;                                 // 0..15
    if (chain >= BB_ * KK_) return;
    const int k = chain % KK_;
    const float a = expf(-10.0f / tau[k]);
    float* ptr = out + (size_t)chain * TT_ * 16 + p;
    float y = ptr[0];
    #pragma unroll 8
    for (int t = 1; t < TT_; t++) {
        const float x = ptr[t * 16];
        y = fmaf(a, y - x, x);            // a*y + (1-a)*x
        ptr[t * 16] = y;
    }
}

extern "C" void kernel_launch(void* const* d_in, const int* in_sizes, int n_in,
                              void* d_out, int out_size)
{
    const float* bins_re = (const float*)d_in[0];
    const float* bins_im = (const float*)d_in[1];
    const float* band_re = (const float*)d_in[2];
    const float* band_im = (const float*)d_in[3];
    const float* c2pv_re = (const float*)d_in[4];
    const float* c2pv_im = (const float*)d_in[5];
    const float* tau     = (const float*)d_in[6];
    float* out = (float*)d_out;

    const size_t smem_bytes =
        (size_t)(FF_ * 16 * 2 + KK_ * 16 * 2 + 2 * CHF_ + 2 * TILE_ * KK_ + 512 + 48)
        * sizeof(float);  // 97,632 B

    cudaFuncSetAttribute(pv_main_kernel,
                         cudaFuncAttributeMaxDynamicSharedMemorySize,
                         (int)smem_bytes);

    dim3 grid(TT_, BB_);
    pv_main_kernel<<<grid, NTH_, smem_bytes>>>(bins_re, bins_im, band_re, band_im,
                                               c2pv_re, c2pv_im, out);

    dim3 blk2(16, 8);
    dim3 g2((BB_ * KK_) / 8);
    pv_iir_kernel<<<g2, blk2>>>(out, tau);
}

// round 3
// speedup vs baseline: 2.4994x; 2.4994x over previous
#include <cuda_runtime.h>

#define FF   481
#define KK   48
#define TT   1024
#define BB   4
#define NTH  192
#define TB   2              // frames per block
#define TILE 32             // band f-tile

// ---------------------------------------------------------------------------
__device__ float g_invds[KK];

__device__ __forceinline__ float frsqrt_a(float x) {
    float r; asm("rsqrt.approx.f32 %0, %1;" : "=f"(r) : "f"(x)); return r;
}
__device__ __forceinline__ float frcp_a(float x) {
    float r; asm("rcp.approx.f32 %0, %1;" : "=f"(r) : "f"(x)); return r;
}

// ds[k] = sum_f band_re[f,k]  (Sum over DIAG of adj == 1 identically)
__global__ void pv_invds_kernel(const float* __restrict__ band_re)
{
    int k = threadIdx.x;
    if (k < KK) {
        float s = 0.f;
        for (int f = 0; f < FF; f++) s += band_re[f * KK + k];
        g_invds[k] = 1.0f / fmaxf(s, 1e-20f);
    }
}

// ---------------------------------------------------------------------------
// Main: per block processes TB frames. Phase A builds compressed Hermitian
// adj (16 reals per f) via the rank-1 identity; Phase B is a real
// (16 x F) x (F x 96) accumulation; epilogue reconstructs bc, projects with
// c2pv, scales by the constant 1/ds, stores (IIR applied later, it commutes).
__global__ __launch_bounds__(NTH, 2)
void pv_main_kernel(const float* __restrict__ bins_re,
                    const float* __restrict__ bins_im,
                    const float* __restrict__ band_re,
                    const float* __restrict__ band_im,
                    const float* __restrict__ c2pv_re,
                    const float* __restrict__ c2pv_im,
                    float* __restrict__ out)
{
    extern __shared__ float smem[];
    float4* adjc4 = (float4*)smem;                  // [TB][FF][4] float4
    float*  dyn   = smem + TB * FF * 16;            // union region (5772 floats)
    // Phase A view:
    float* xs  = dyn;                               // [2][4][FF]  re then im (3848)
    float* rsd = dyn + 2 * 4 * FF;                  // [4][FF]     (1924)
    // Phase B view:
    float* btT = dyn;                               // [KK][33]    (1584)
    float* biT = dyn + 1584;                        // [KK][33]
    float* bcs = dyn + 3168;                        // [KK][33]    (re,im)*16 padded
    float* c2s = dyn + 4752;                        // [512]

    const int tid = threadIdx.x;
    const int b   = blockIdx.y;
    const int t0  = blockIdx.x * TB;

    // ======================= Phase A (per frame) ===========================
    for (int bt = 0; bt < TB; bt++) {
        __syncthreads();
        const size_t base = (size_t)(b * TT + t0 + bt) * (4 * FF);
        for (int i = tid; i < 4 * FF; i += NTH) {
            xs[i]          = bins_re[base + i];
            xs[4*FF + i]   = bins_im[base + i];
        }
        __syncthreads();
        // A1: per (ch,f): rsd = rsqrt(|x|^2)
        for (int i = tid; i < 4 * FF; i += NTH) {
            const float xr = xs[i], xi = xs[4*FF + i];
            rsd[i] = frsqrt_a(fmaxf(xr*xr + xi*xi, 1e-35f));
        }
        __syncthreads();
        // A2: build compressed adj
        for (int f = tid; f < FF; f += NTH) {
            int fm = f - 1;
            if (fm < 0) fm = 0;
            if (fm > FF - 3) fm = FF - 3;
            const int fp = fm + 2;

            float yr[4], yi[4], dv[4];
            #pragma unroll
            for (int ch = 0; ch < 4; ch++) {
                const int ix = ch * FF;
                const float xr  = xs[ix + f],  xi_ = xs[4*FF + ix + f];
                const float mrr = xs[ix + fm], mii = xs[4*FF + ix + fm];
                const float prr = xs[ix + fp], pii = xs[4*FF + ix + fp];
                const float d   = xr*xr + xi_*xi_;
                dv[ch] = d;
                // u = conj(x_fm) * x_fp
                const float ur = mrr*prr + mii*pii;
                const float ui = mrr*pii - mii*prr;
                // y = |x_f| * unit(u)   (|u| = |x_fm||x_fp|)
                const float s = d * rsd[ix + f] * rsd[ix + fm] * rsd[ix + fp];
                yr[ch] = s * ur;  yi[ch] = s * ui;
            }
            const float invp = frcp_a(fmaxf(dv[0] + dv[1] + dv[2] + dv[3], 1e-20f));
            const float l0r = yr[0]*invp, l0i = yi[0]*invp;
            const float l1r = yr[1]*invp, l1i = yi[1]*invp;
            const float l2r = yr[2]*invp, l2i = yi[2]*invp;
            // v_ij = invp * y_i * conj(y_j)
            const float v01r = l0r*yr[1] + l0i*yi[1], v01i = l0i*yr[1] - l0r*yi[1];
            const float v02r = l0r*yr[2] + l0i*yi[2], v02i = l0i*yr[2] - l0r*yi[2];
            const float v03r = l0r*yr[3] + l0i*yi[3], v03i = l0i*yr[3] - l0r*yi[3];
            const float v12r = l1r*yr[2] + l1i*yi[2], v12i = l1i*yr[2] - l1r*yi[2];
            const float v13r = l1r*yr[3] + l1i*yi[3], v13i = l1i*yr[3] - l1r*yi[3];
            const float v23r = l2r*yr[3] + l2i*yi[3], v23i = l2i*yr[3] - l2r*yi[3];

            float4* row = adjc4 + (size_t)(bt * FF + f) * 4;
            row[0] = make_float4(dv[0]*invp, dv[1]*invp, v01r, v01i);
            row[1] = make_float4(dv[2]*invp, dv[3]*invp, v23r, v23i);
            row[2] = make_float4(v02r, v02i, v13r, v13i);
            row[3] = make_float4(v03r, v03i, v12r, v12i);
        }
    }
    __syncthreads();

    // c2pv into smem (aliases rsd region — Phase A fully done)
    for (int i = tid; i < 256; i += NTH) {
        c2s[i]       = c2pv_re[i];
        c2s[256 + i] = c2pv_im[i];
    }

    // ======================= Phase B: real GEMM ============================
    const int k = tid % KK;        // band
    const int g = tid / KK;        // float4 group 0..3
    float4 S0r = {0,0,0,0}, S0i = {0,0,0,0};   // bt0: sum(val*br), sum(val*bi)
    float4 S1r = {0,0,0,0}, S1i = {0,0,0,0};   // bt1

    const float*  btk = btT + k * 33;
    const float*  bik = biT + k * 33;

    for (int f0 = 0; f0 < FF; f0 += TILE) {
        const int nf = (FF - f0 < TILE) ? (FF - f0) : TILE;
        __syncthreads();
        for (int i = tid; i < nf * KK; i += NTH) {
            const int ff = i / KK, kk = i % KK;
            btT[kk * 33 + ff] = band_re[(f0 + ff) * KK + kk];
            biT[kk * 33 + ff] = band_im[(f0 + ff) * KK + kk];
        }
        __syncthreads();
        const float4* a0p = adjc4 + (size_t)f0 * 4 + g;
        const float4* a1p = a0p + (size_t)FF * 4;
        if (nf == TILE) {
            #pragma unroll 8
            for (int ff = 0; ff < TILE; ff++) {
                const float br = btk[ff], bi = bik[ff];
                const float4 a0 = a0p[ff * 4];
                const float4 a1 = a1p[ff * 4];
                S0r.x = fmaf(a0.x, br, S0r.x); S0i.x = fmaf(a0.x, bi, S0i.x);
                S0r.y = fmaf(a0.y, br, S0r.y); S0i.y = fmaf(a0.y, bi, S0i.y);
                S0r.z = fmaf(a0.z, br, S0r.z); S0i.z = fmaf(a0.z, bi, S0i.z);
                S0r.w = fmaf(a0.w, br, S0r.w); S0i.w = fmaf(a0.w, bi, S0i.w);
                S1r.x = fmaf(a1.x, br, S1r.x); S1i.x = fmaf(a1.x, bi, S1i.x);
                S1r.y = fmaf(a1.y, br, S1r.y); S1i.y = fmaf(a1.y, bi, S1i.y);
                S1r.z = fmaf(a1.z, br, S1r.z); S1i.z = fmaf(a1.z, bi, S1i.z);
                S1r.w = fmaf(a1.w, br, S1r.w); S1i.w = fmaf(a1.w, bi, S1i.w);
            }
        } else {
            for (int ff = 0; ff < nf; ff++) {
                const float br = btk[ff], bi = bik[ff];
                const float4 a0 = a0p[ff * 4];
                const float4 a1 = a1p[ff * 4];
                S0r.x = fmaf(a0.x, br, S0r.x); S0i.x = fmaf(a0.x, bi, S0i.x);
                S0r.y = fmaf(a0.y, br, S0r.y); S0i.y = fmaf(a0.y, bi, S0i.y);
                S0r.z = fmaf(a0.z, br, S0r.z); S0i.z = fmaf(a0.z, bi, S0i.z);
                S0r.w = fmaf(a0.w, br, S0r.w); S0i.w = fmaf(a0.w, bi, S0i.w);
                S1r.x = fmaf(a1.x, br, S1r.x); S1i.x = fmaf(a1.x, bi, S1i.x);
                S1r.y = fmaf(a1.y, br, S1r.y); S1i.y = fmaf(a1.y, bi, S1i.y);
                S1r.z = fmaf(a1.z, br, S1r.z); S1i.z = fmaf(a1.z, bi, S1i.z);
                S1r.w = fmaf(a1.w, br, S1r.w); S1i.w = fmaf(a1.w, bi, S1i.w);
            }
        }
    }

    // ======================= Epilogue ======================================
    const float invd = g_invds[k];
    #pragma unroll
    for (int bt = 0; bt < TB; bt++) {
        const float4 Sr = bt ? S1r : S0r;
        const float4 Si = bt ? S1i : S0i;
        __syncthreads();
        float* bk = bcs + k * 33;
        if (g < 2) {
            // diag pair + off-diag pair (0,1) or (2,3)
            const int cd0 = g ? 10 : 0, cd1 = g ? 15 : 5;
            const int cpa = g ? 11 : 1, cpb = g ? 14 : 4;
            bk[2*cd0] = Sr.x;  bk[2*cd0+1] = Si.x;
            bk[2*cd1] = Sr.y;  bk[2*cd1+1] = Si.y;
            bk[2*cpa] = Sr.z - Si.w;  bk[2*cpa+1] = Si.z + Sr.w;
            bk[2*cpb] = Sr.z + Si.w;  bk[2*cpb+1] = Si.z - Sr.w;
        } else {
            // g2: pairs (0,2)->c2/c8, (1,3)->c7/c13 ; g3: (0,3)->c3/c12, (1,2)->c6/c9
            const int ca = (g == 2) ? 2 : 3,  cb = (g == 2) ? 8  : 12;
            const int cc = (g == 2) ? 7 : 6,  cd = (g == 2) ? 13 : 9;
            bk[2*ca] = Sr.x - Si.y;  bk[2*ca+1] = Si.x + Sr.y;
            bk[2*cb] = Sr.x + Si.y;  bk[2*cb+1] = Si.x - Sr.y;
            bk[2*cc] = Sr.z - Si.w;  bk[2*cc+1] = Si.z + Sr.w;
            bk[2*cd] = Sr.z + Si.w;  bk[2*cd+1] = Si.z - Sr.w;
        }
        __syncthreads();
        // projection: pv[p] = sum_c c2r[p,c]*bc_r - c2i[p,c]*bc_i
        const int p0 = g * 4;
        float acc0 = 0.f, acc1 = 0.f, acc2 = 0.f, acc3 = 0.f;
        #pragma unroll
        for (int c = 0; c < 16; c++) {
            const float vr = bk[2*c], vi = bk[2*c+1];
            acc0 += c2s[(p0+0)*16 + c]*vr - c2s[256 + (p0+0)*16 + c]*vi;
            acc1 += c2s[(p0+1)*16 + c]*vr - c2s[256 + (p0+1)*16 + c]*vi;
            acc2 += c2s[(p0+2)*16 + c]*vr - c2s[256 + (p0+2)*16 + c]*vi;
            acc3 += c2s[(p0+3)*16 + c]*vr - c2s[256 + (p0+3)*16 + c]*vi;
        }
        float4 o = make_float4(acc0*invd, acc1*invd, acc2*invd, acc3*invd);
        const size_t ob = (((size_t)(b * KK + k)) * TT + (t0 + bt)) * 16 + p0;
        *(float4*)(out + ob) = o;
    }
}

// ---------------------------------------------------------------------------
// IIR as a chunked parallel scan: 16 chunks of 64 per chain, register-resident.
__global__ __launch_bounds__(256)
void pv_iir_kernel(float* __restrict__ out, const float* __restrict__ tau)
{
    __shared__ float Lend[256];
    __shared__ float Cin[256];

    const int chain = blockIdx.x;          // b*KK + k
    const int k  = chain % KK;
    const int p  = threadIdx.x & 15;
    const int c  = threadIdx.x >> 4;       // chunk 0..15
    const float a = expf(-10.0f / tau[k]);
    const float bco = 1.0f - a;

    float* base = out + (size_t)chain * (TT * 16) + (size_t)c * 64 * 16 + p;

    float v[64];
    #pragma unroll
    for (int i = 0; i < 64; i++) v[i] = base[i * 16];

    // local scan (chunk 0 keeps y0 = x0; others start with zero carry)
    float y = (c == 0) ? v[0] : bco * v[0];
    v[0] = y;
    #pragma unroll
    for (int i = 1; i < 64; i++) { y = fmaf(a, y, bco * v[i]); v[i] = y; }

    // a^64 by repeated squaring
    float A = a;
    #pragma unroll
    for (int s = 0; s < 6; s++) A *= A;

    Lend[c * 16 + p] = y;
    __syncthreads();
    if (threadIdx.x < 16) {                 // one thread per p: serial over chunks
        float carry = 0.f;
        #pragma unroll
        for (int cc = 0; cc < 16; cc++) {
            Cin[cc * 16 + threadIdx.x] = carry;
            carry = Lend[cc * 16 + threadIdx.x] + A * carry;
        }
    }
    __syncthreads();

    const float carry = Cin[c * 16 + p];
    float pw = a;
    #pragma unroll
    for (int i = 0; i < 64; i++) {
        base[i * 16] = v[i] + pw * carry;
        pw *= a;
    }
}

// ---------------------------------------------------------------------------
extern "C" void kernel_launch(void* const* d_in, const int* in_sizes, int n_in,
                              void* d_out, int out_size)
{
    const float* bins_re = (const float*)d_in[0];
    const float* bins_im = (const float*)d_in[1];
    const float* band_re = (const float*)d_in[2];
    const float* band_im = (const float*)d_in[3];
    const float* c2pv_re = (const float*)d_in[4];
    const float* c2pv_im = (const float*)d_in[5];
    const float* tau     = (const float*)d_in[6];
    float* out = (float*)d_out;

    const size_t smem_bytes = (size_t)(TB * FF * 16 + 5772) * sizeof(float); // ~84.7KB
    static int configured = 0;
    cudaFuncSetAttribute(pv_main_kernel,
                         cudaFuncAttributeMaxDynamicSharedMemorySize,
                         (int)smem_bytes);
    (void)configured;

    pv_invds_kernel<<<1, KK>>>(band_re);

    dim3 grid(TT / TB, BB);
    pv_main_kernel<<<grid, NTH, smem_bytes>>>(bins_re, bins_im, band_re, band_im,
                                              c2pv_re, c2pv_im, out);

    pv_iir_kernel<<<BB * KK, 256>>>(out, tau);
}

// round 8
// speedup vs baseline: 5.2359x; 2.0949x over previous
#include <cuda_runtime.h>
#include <cuda_bf16.h>
#include <cstdint>

#define FF 481
#define KK 48
#define TT 1024
#define BB 4
#define FPC 8            // frames per CTA (8 warps, warp <-> frame)
#define NTH 256
#define KC 64            // f per chunk
#define NCHUNK 8
#define KPAD 512         // 8 * 64

// smem byte offsets. A/B tiles stride 72 bf16 = 144 B (ldmatrix conflict-free).
#define OFF_AH   0               // 128 x 72 bf16 = 18432
#define OFF_AL   18432
#define OFF_BH   36864           // 96 x 72 bf16 = 13824
#define OFF_BL   50688
#define OFF_XS   64512           // 64 rows x 68 floats = 17408 B
#define OFF_C2   81920           // 512 floats
#define SMEM_BYTES 83968
#define OFF_DSM  0               // epilogue alias: 128*97 floats = 49664 B

__device__ float g_invds[KK];
__device__ __align__(16) __nv_bfloat16 g_Bh[96 * KPAD];
__device__ __align__(16) __nv_bfloat16 g_Bl[96 * KPAD];

// ---------------------------------------------------------------------------
__device__ __forceinline__ float frsqrt_a(float x) {
    float r; asm("rsqrt.approx.f32 %0, %1;" : "=f"(r) : "f"(x)); return r;
}
__device__ __forceinline__ float frcp_a(float x) {
    float r; asm("rcp.approx.f32 %0, %1;" : "=f"(r) : "f"(x)); return r;
}
__device__ __forceinline__ uint32_t smem_u32(const void* p) {
    uint32_t a;
    asm("{ .reg .u64 t; cvta.to.shared.u64 t, %1; cvt.u32.u64 %0, t; }" : "=r"(a) : "l"(p));
    return a;
}

#define LDSM4(r, a)                                                          \
    asm volatile("ldmatrix.sync.aligned.m8n8.x4.shared.b16 {%0,%1,%2,%3}, [%4];" \
        : "=r"((r)[0]), "=r"((r)[1]), "=r"((r)[2]), "=r"((r)[3]) : "r"(a))

#define MMA16816(c, a, b0, b1)                                               \
    asm volatile("mma.sync.aligned.m16n8k16.row.col.f32.bf16.bf16.f32 "      \
        "{%0,%1,%2,%3}, {%4,%5,%6,%7}, {%8,%9}, {%0,%1,%2,%3};"              \
        : "+f"((c)[0]), "+f"((c)[1]), "+f"((c)[2]), "+f"((c)[3])             \
        : "r"((a)[0]), "r"((a)[1]), "r"((a)[2]), "r"((a)[3]),                \
          "r"(b0), "r"(b1))

// ---------------------------------------------------------------------------
// Prep: band -> bf16 hi/lo, layout [96 rows n][KPAD]. n<48: band_re[:,n];
// n>=48: band_im[:,n-48]. Zero-padded for f>=481.
__global__ void pv_prep_b(const float* __restrict__ band_re,
                          const float* __restrict__ band_im)
{
    const int idx = blockIdx.x * 256 + threadIdx.x;
    if (idx >= 96 * KPAD) return;
    const int n = idx >> 9, f = idx & (KPAD - 1);
    float v = 0.f;
    if (f < FF) v = (n < KK) ? band_re[f * KK + n] : band_im[f * KK + (n - KK)];
    const __nv_bfloat16 h = __float2bfloat16(v);
    g_Bh[idx] = h;
    g_Bl[idx] = __float2bfloat16(v - __bfloat162float(h));
}

__global__ void pv_invds(const float* __restrict__ band_re)
{
    const int k = blockIdx.x;
    float s = 0.f;
    for (int f = threadIdx.x; f < FF; f += 128) s += band_re[f * KK + k];
    __shared__ float red[4];
    #pragma unroll
    for (int o = 16; o; o >>= 1) s += __shfl_xor_sync(0xffffffffu, s, o);
    if ((threadIdx.x & 31) == 0) red[threadIdx.x >> 5] = s;
    __syncthreads();
    if (threadIdx.x == 0)
        g_invds[k] = 1.0f / fmaxf(red[0] + red[1] + red[2] + red[3], 1e-20f);
}

// ---------------------------------------------------------------------------
// Phase A per frequency: compressed 16-real Hermitian phase-adjusted cov.
__device__ __forceinline__ void phaseA_f(const float* __restrict__ xb,
                                         int xl, int ml, int pl, float* v)
{
    float yr[4], yi[4], dv[4];
    float dsum = 0.f;
    #pragma unroll
    for (int ch = 0; ch < 4; ch++) {
        const float* rr = xb + ch * 136;
        const float* ii = rr + 68;
        const float xr = rr[xl], xi = ii[xl];
        const float mr = rr[ml], mi = ii[ml];
        const float pr = rr[pl], pi = ii[pl];
        const float d  = xr * xr + xi * xi;
        const float dm = mr * mr + mi * mi;
        const float dp = pr * pr + pi * pi;
        const float ur = mr * pr + mi * pi;       // conj(x_fm) * x_fp
        const float ui = mr * pi - mi * pr;
        const float s  = d * frsqrt_a(fmaxf(d * dm * dp, 1e-38f)); // = |x_f|/|u|
        yr[ch] = s * ur; yi[ch] = s * ui;
        dv[ch] = d; dsum += d;
    }
    const float invp = frcp_a(fmaxf(dsum, 1e-20f));
    const float l0r = yr[0] * invp, l0i = yi[0] * invp;
    const float l1r = yr[1] * invp, l1i = yi[1] * invp;
    const float l2r = yr[2] * invp, l2i = yi[2] * invp;
    v[0]  = dv[0] * invp;  v[1]  = dv[1] * invp;
    v[2]  = l0r*yr[1] + l0i*yi[1];  v[3]  = l0i*yr[1] - l0r*yi[1];   // v01
    v[4]  = dv[2] * invp;  v[5]  = dv[3] * invp;
    v[6]  = l2r*yr[3] + l2i*yi[3];  v[7]  = l2i*yr[3] - l2r*yi[3];   // v23
    v[8]  = l0r*yr[2] + l0i*yi[2];  v[9]  = l0i*yr[2] - l0r*yi[2];   // v02
    v[10] = l1r*yr[3] + l1i*yi[3];  v[11] = l1i*yr[3] - l1r*yi[3];   // v13
    v[12] = l0r*yr[3] + l0i*yi[3];  v[13] = l0i*yr[3] - l0r*yi[3];   // v03
    v[14] = l1r*yr[2] + l1i*yi[2];  v[15] = l1i*yr[2] - l1r*yi[2];   // v12
}

// ---------------------------------------------------------------------------
__global__ __launch_bounds__(NTH, 2)
void pv_main(const float* __restrict__ bins_re, const float* __restrict__ bins_im,
             const float* __restrict__ c2pv_re, const float* __restrict__ c2pv_im,
             float* __restrict__ out)
{
    extern __shared__ unsigned char smem[];
    float* smf = (float*)smem;
    const uint32_t sb = smem_u32(smem);
    const int tid = threadIdx.x;
    const int wid = tid >> 5;
    const int lid = tid & 31;
    const int b   = blockIdx.y;
    const int t0  = blockIdx.x * FPC;

    float* c2s = smf + OFF_C2 / 4;
    for (int i = tid; i < 256; i += NTH) {
        c2s[i] = c2pv_re[i]; c2s[256 + i] = c2pv_im[i];
    }

    float* xs = smf + OFF_XS / 4;   // [64 rows][68]; row = fr*8 + ch*2 + im

    // ldmatrix lane address components (fixed per thread)
    const int rowA  = wid * 16 + (lid & 7) + ((lid >> 3) & 1) * 8;
    const int koffA = (lid >> 4) * 8;
    const int nB    = (lid & 7) + ((lid >> 4) << 3);
    const int kB    = ((lid >> 3) & 1) * 8;

    float acc[12][4];
    #pragma unroll
    for (int nb = 0; nb < 12; nb++) {
        acc[nb][0] = 0.f; acc[nb][1] = 0.f; acc[nb][2] = 0.f; acc[nb][3] = 0.f;
    }

    for (int chunk = 0; chunk < NCHUNK; chunk++) {
        const int f0 = chunk * KC;
        __syncthreads();   // previous chunk's tile reads done

        // stage bins slab: local j=0..65 <-> global f0-1+j (clamped)
        for (int i = tid; i < 64 * 66; i += NTH) {
            const int row = i / 66, j = i - row * 66;
            const int fr = row >> 3, ch = (row >> 1) & 3, im = row & 1;
            int gf = f0 - 1 + j;
            gf = gf < 0 ? 0 : (gf > FF - 1 ? FF - 1 : gf);
            const float* src = im ? bins_im : bins_re;
            xs[row * 68 + j] = src[((size_t)((b * TT + t0 + fr) * 4 + ch)) * FF + gf];
        }
        // copy B tiles (hi/lo): 96 rows x 64 bf16 -> stride 72
        for (int i = tid; i < 768; i += NTH) {
            const int row = i >> 3, q = i & 7;
            const uint4 vh = *(const uint4*)(g_Bh + row * KPAD + f0 + q * 8);
            const uint4 vl = *(const uint4*)(g_Bl + row * KPAD + f0 + q * 8);
            *(uint4*)(smem + OFF_BH + row * 144 + q * 16) = vh;
            *(uint4*)(smem + OFF_BL + row * 144 + q * 16) = vl;
        }
        __syncthreads();

        // Phase A: this thread handles f-pair (fl, fl+1) of frame `wid`
        const float* xb = xs + wid * 8 * 68;
        const int fl = lid * 2;
        float v0[16], v1[16];
        {
            const int f = f0 + fl;
            if (f < FF) {
                const int fm = (f - 1 < 0) ? 0 : ((f - 1 > FF - 3) ? FF - 3 : f - 1);
                phaseA_f(xb, f - f0 + 1, fm - f0 + 1, fm - f0 + 3, v0);
            } else {
                for (int c = 0; c < 16; c++) v0[c] = 0.f;
            }
        }
        {
            const int f = f0 + fl + 1;
            if (f < FF) {
                const int fm = (f - 1 > FF - 3) ? FF - 3 : f - 1;
                phaseA_f(xb, f - f0 + 1, fm - f0 + 1, fm - f0 + 3, v1);
            } else {
                for (int c = 0; c < 16; c++) v1[c] = 0.f;
            }
        }
        #pragma unroll
        for (int c = 0; c < 16; c++) {
            const int row = wid * 16 + c;
            __nv_bfloat162 h;
            h.x = __float2bfloat16(v0[c]); h.y = __float2bfloat16(v1[c]);
            *(__nv_bfloat162*)(smem + OFF_AH + row * 144 + fl * 2) = h;
            __nv_bfloat162 l;
            l.x = __float2bfloat16(v0[c] - __bfloat162float(h.x));
            l.y = __float2bfloat16(v1[c] - __bfloat162float(h.y));
            *(__nv_bfloat162*)(smem + OFF_AL + row * 144 + fl * 2) = l;
        }
        __syncthreads();

        // MMA: 4 k-steps x 12 n-blocks x 3 split-products
        #pragma unroll
        for (int ks = 0; ks < 4; ks++) {
            const int k0 = ks * 16;
            const uint32_t aA = sb + OFF_AH + rowA * 144 + (k0 + koffA) * 2;
            uint32_t ah[4], al[4];
            LDSM4(ah, aA);
            LDSM4(al, aA + (OFF_AL - OFF_AH));
            #pragma unroll
            for (int nbp = 0; nbp < 6; nbp++) {
                const uint32_t aB = sb + OFF_BH + (nbp * 16 + nB) * 144 + (k0 + kB) * 2;
                uint32_t bh[4], bl[4];
                LDSM4(bh, aB);
                LDSM4(bl, aB + (OFF_BL - OFF_BH));
                MMA16816(acc[2*nbp],     ah, bh[0], bh[1]);
                MMA16816(acc[2*nbp],     al, bh[0], bh[1]);
                MMA16816(acc[2*nbp],     ah, bl[0], bl[1]);
                MMA16816(acc[2*nbp + 1], ah, bh[2], bh[3]);
                MMA16816(acc[2*nbp + 1], al, bh[2], bh[3]);
                MMA16816(acc[2*nbp + 1], ah, bl[2], bl[3]);
            }
        }
    }
    __syncthreads();

    // accumulators -> Dsm [128 m][97 stride]
    float* Dsm = smf + OFF_DSM / 4;
    {
        const int m0 = wid * 16 + (lid >> 2);
        const int ncol = (lid & 3) * 2;
        #pragma unroll
        for (int nb = 0; nb < 12; nb++) {
            const int n0 = nb * 8 + ncol;
            Dsm[m0 * 97 + n0]           = acc[nb][0];
            Dsm[m0 * 97 + n0 + 1]       = acc[nb][1];
            Dsm[(m0 + 8) * 97 + n0]     = acc[nb][2];
            Dsm[(m0 + 8) * 97 + n0 + 1] = acc[nb][3];
        }
    }
    __syncthreads();

    // Epilogue: reconstruct Hermitian bc, project with c2pv, scale, store
    if (tid < 192) {
        const int k = tid % KK, g = tid / KK, p0 = g * 4;
        const float invd = g_invds[k];
        for (int fr = 0; fr < FPC; fr++) {
            float sr[16], si[16];
            #pragma unroll
            for (int c = 0; c < 16; c++) {
                sr[c] = Dsm[(fr * 16 + c) * 97 + k];
                si[c] = Dsm[(fr * 16 + c) * 97 + 48 + k];
            }
            float br[16], bi[16];
            br[0]=sr[0];  bi[0]=si[0];   br[5]=sr[1];   bi[5]=si[1];
            br[10]=sr[4]; bi[10]=si[4];  br[15]=sr[5];  bi[15]=si[5];
            br[1]=sr[2]-si[3];    bi[1]=si[2]+sr[3];
            br[4]=sr[2]+si[3];    bi[4]=si[2]-sr[3];
            br[11]=sr[6]-si[7];   bi[11]=si[6]+sr[7];
            br[14]=sr[6]+si[7];   bi[14]=si[6]-sr[7];
            br[2]=sr[8]-si[9];    bi[2]=si[8]+sr[9];
            br[8]=sr[8]+si[9];    bi[8]=si[8]-sr[9];
            br[7]=sr[10]-si[11];  bi[7]=si[10]+sr[11];
            br[13]=sr[10]+si[11]; bi[13]=si[10]-sr[11];
            br[3]=sr[12]-si[13];  bi[3]=si[12]+sr[13];
            br[12]=sr[12]+si[13]; bi[12]=si[12]-sr[13];
            br[6]=sr[14]-si[15];  bi[6]=si[14]+sr[15];
            br[9]=sr[14]+si[15];  bi[9]=si[14]-sr[15];
            float a0=0.f, a1=0.f, a2=0.f, a3=0.f;
            #pragma unroll
            for (int c = 0; c < 16; c++) {
                const float vr = br[c], vi = bi[c];
                a0 = fmaf(c2s[(p0+0)*16+c], vr, a0); a0 = fmaf(-c2s[256+(p0+0)*16+c], vi, a0);
                a1 = fmaf(c2s[(p0+1)*16+c], vr, a1); a1 = fmaf(-c2s[256+(p0+1)*16+c], vi, a1);
                a2 = fmaf(c2s[(p0+2)*16+c], vr, a2); a2 = fmaf(-c2s[256+(p0+2)*16+c], vi, a2);
                a3 = fmaf(c2s[(p0+3)*16+c], vr, a3); a3 = fmaf(-c2s[256+(p0+3)*16+c], vi, a3);
            }
            float4 o = make_float4(a0*invd, a1*invd, a2*invd, a3*invd);
            *(float4*)(out + (((size_t)(b * KK + k)) * TT + (t0 + fr)) * 16 + p0) = o;
        }
    }
}

// ---------------------------------------------------------------------------
// IIR: chunked parallel scan, in-place on out (B,K,T,16). Real IIR commutes
// with the real-linear c2pv projection, so smoothing projected values is exact.
__global__ __launch_bounds__(256)
void pv_iir(float* __restrict__ out, const float* __restrict__ tau)
{
    __shared__ float Lend[256];
    __shared__ float Cin[256];
    const int chain = blockIdx.x;
    const int k = chain % KK;
    const int p = threadIdx.x & 15;
    const int c = threadIdx.x >> 4;
    const float a = expf(-10.0f / tau[k]);
    const float bco = 1.0f - a;
    float* base = out + (size_t)chain * (TT * 16) + (size_t)c * 64 * 16 + p;

    float v[64];
    #pragma unroll
    for (int i = 0; i < 64; i++) v[i] = base[i * 16];
    float y = (c == 0) ? v[0] : bco * v[0];
    v[0] = y;
    #pragma unroll
    for (int i = 1; i < 64; i++) { y = fmaf(a, y, bco * v[i]); v[i] = y; }

    float A = a;
    #pragma unroll
    for (int s = 0; s < 6; s++) A *= A;           // a^64

    Lend[c * 16 + p] = y;
    __syncthreads();
    if (threadIdx.x < 16) {
        float carry = 0.f;
        #pragma unroll
        for (int cc = 0; cc < 16; cc++) {
            Cin[cc * 16 + threadIdx.x] = carry;
            carry = Lend[cc * 16 + threadIdx.x] + A * carry;
        }
    }
    __syncthreads();
    const float carry = Cin[c * 16 + p];
    float pw = a;
    #pragma unroll
    for (int i = 0; i < 64; i++) { base[i * 16] = v[i] + pw * carry; pw *= a; }
}

// ---------------------------------------------------------------------------
extern "C" void kernel_launch(void* const* d_in, const int* in_sizes, int n_in,
                              void* d_out, int out_size)
{
    const float* bins_re = (const float*)d_in[0];
    const float* bins_im = (const float*)d_in[1];
    const float* band_re = (const float*)d_in[2];
    const float* band_im = (const float*)d_in[3];
    const float* c2pv_re = (const float*)d_in[4];
    const float* c2pv_im = (const float*)d_in[5];
    const float* tau     = (const float*)d_in[6];
    float* out = (float*)d_out;

    cudaFuncSetAttribute(pv_main, cudaFuncAttributeMaxDynamicSharedMemorySize,
                         SMEM_BYTES);

    pv_prep_b<<<(96 * KPAD + 255) / 256, 256>>>(band_re, band_im);
    pv_invds<<<KK, 128>>>(band_re);

    dim3 grid(TT / FPC, BB);
    pv_main<<<grid, NTH, SMEM_BYTES>>>(bins_re, bins_im, c2pv_re, c2pv_im, out);

    pv_iir<<<BB * KK, 256>>>(out, tau);
}

// round 11
// speedup vs baseline: 6.1321x; 1.1712x over previous
#include <cuda_runtime.h>
#include <cuda_bf16.h>
#include <cstdint>

#define FF 481
#define KK 48
#define TT 1024
#define BB 4
#define FPC 8            // frames per CTA (8 warps, warp <-> frame)
#define NTH 256
#define KC 64            // f per chunk
#define NCHUNK 8
#define KPAD 512         // 8 * 64

// smem byte offsets. A/B tiles row stride 72 bf16 = 144 B (ldmatrix conflict-free).
#define OFF_AH   0               // 128 x 72 bf16 = 18432
#define OFF_AL   18432
#define OFF_B0H  36864           // 96 x 72 bf16 = 13824
#define OFF_B0L  50688
#define OFF_B1H  64512
#define OFF_B1L  78336
#define OFF_XS   92160           // 64 rows x 68 floats = 17408
#define OFF_C2   109568          // 512 floats = 2048
#define SMEM_BYTES 111616
#define OFF_DSM  0               // epilogue alias: 128*97 floats = 49664 B

__device__ float g_invds[KK];
__device__ __align__(16) __nv_bfloat16 g_Bh[96 * KPAD];
__device__ __align__(16) __nv_bfloat16 g_Bl[96 * KPAD];

// ---------------------------------------------------------------------------
__device__ __forceinline__ float frsqrt_a(float x) {
    float r; asm("rsqrt.approx.f32 %0, %1;" : "=f"(r) : "f"(x)); return r;
}
__device__ __forceinline__ float frcp_a(float x) {
    float r; asm("rcp.approx.f32 %0, %1;" : "=f"(r) : "f"(x)); return r;
}
__device__ __forceinline__ uint32_t smem_u32(const void* p) {
    uint32_t a;
    asm("{ .reg .u64 t; cvta.to.shared.u64 t, %1; cvt.u32.u64 %0, t; }" : "=r"(a) : "l"(p));
    return a;
}

#define CP4(dst, src)  asm volatile("cp.async.ca.shared.global [%0], [%1], 4;"  :: "r"(dst), "l"(src))
#define CP16(dst, src) asm volatile("cp.async.cg.shared.global [%0], [%1], 16;" :: "r"(dst), "l"(src))
#define CP_COMMIT()    asm volatile("cp.async.commit_group;" ::: "memory")
#define CP_WAIT0()     asm volatile("cp.async.wait_group 0;" ::: "memory")

#define LDSM4(r, a)                                                          \
    asm volatile("ldmatrix.sync.aligned.m8n8.x4.shared.b16 {%0,%1,%2,%3}, [%4];" \
        : "=r"((r)[0]), "=r"((r)[1]), "=r"((r)[2]), "=r"((r)[3]) : "r"(a))

#define MMA16816(c, a, b0, b1)                                               \
    asm volatile("mma.sync.aligned.m16n8k16.row.col.f32.bf16.bf16.f32 "      \
        "{%0,%1,%2,%3}, {%4,%5,%6,%7}, {%8,%9}, {%0,%1,%2,%3};"              \
        : "+f"((c)[0]), "+f"((c)[1]), "+f"((c)[2]), "+f"((c)[3])             \
        : "r"((a)[0]), "r"((a)[1]), "r"((a)[2]), "r"((a)[3]),                \
          "r"(b0), "r"(b1))

// ---------------------------------------------------------------------------
// Prep: band -> bf16 hi/lo, layout [96 rows n][KPAD]. n<48: band_re[:,n];
// n>=48: band_im[:,n-48]. Zero-padded for f>=481.
__global__ void pv_prep_b(const float* __restrict__ band_re,
                          const float* __restrict__ band_im)
{
    const int idx = blockIdx.x * 256 + threadIdx.x;
    if (idx >= 96 * KPAD) return;
    const int n = idx >> 9, f = idx & (KPAD - 1);
    float v = 0.f;
    if (f < FF) v = (n < KK) ? band_re[f * KK + n] : band_im[f * KK + (n - KK)];
    const __nv_bfloat16 h = __float2bfloat16(v);
    g_Bh[idx] = h;
    g_Bl[idx] = __float2bfloat16(v - __bfloat162float(h));
}

__global__ void pv_invds(const float* __restrict__ band_re)
{
    const int k = blockIdx.x;
    float s = 0.f;
    for (int f = threadIdx.x; f < FF; f += 128) s += band_re[f * KK + k];
    __shared__ float red[4];
    #pragma unroll
    for (int o = 16; o; o >>= 1) s += __shfl_xor_sync(0xffffffffu, s, o);
    if ((threadIdx.x & 31) == 0) red[threadIdx.x >> 5] = s;
    __syncthreads();
    if (threadIdx.x == 0)
        g_invds[k] = 1.0f / fmaxf(red[0] + red[1] + red[2] + red[3], 1e-20f);
}

// ---------------------------------------------------------------------------
// Phase A per frequency: compressed 16-real Hermitian phase-adjusted cov.
__device__ __forceinline__ void phaseA_f(const float* __restrict__ xb,
                                         int xl, int ml, int pl, float* v)
{
    float yr[4], yi[4], dv[4];
    float dsum = 0.f;
    #pragma unroll
    for (int ch = 0; ch < 4; ch++) {
        const float* rr = xb + ch * 136;
        const float* ii = rr + 68;
        const float xr = rr[xl], xi = ii[xl];
        const float mr = rr[ml], mi = ii[ml];
        const float pr = rr[pl], pi = ii[pl];
        const float d  = xr * xr + xi * xi;
        const float dm = mr * mr + mi * mi;
        const float dp = pr * pr + pi * pi;
        const float ur = mr * pr + mi * pi;       // conj(x_fm) * x_fp
        const float ui = mr * pi - mi * pr;
        const float s  = d * frsqrt_a(fmaxf(d * dm * dp, 1e-38f)); // = |x_f|/|u|
        yr[ch] = s * ur; yi[ch] = s * ui;
        dv[ch] = d; dsum += d;
    }
    const float invp = frcp_a(fmaxf(dsum, 1e-20f));
    const float l0r = yr[0] * invp, l0i = yi[0] * invp;
    const float l1r = yr[1] * invp, l1i = yi[1] * invp;
    const float l2r = yr[2] * invp, l2i = yi[2] * invp;
    v[0]  = dv[0] * invp;  v[1]  = dv[1] * invp;
    v[2]  = l0r*yr[1] + l0i*yi[1];  v[3]  = l0i*yr[1] - l0r*yi[1];   // v01
    v[4]  = dv[2] * invp;  v[5]  = dv[3] * invp;
    v[6]  = l2r*yr[3] + l2i*yi[3];  v[7]  = l2i*yr[3] - l2r*yi[3];   // v23
    v[8]  = l0r*yr[2] + l0i*yi[2];  v[9]  = l0i*yr[2] - l0r*yi[2];   // v02
    v[10] = l1r*yr[3] + l1i*yi[3];  v[11] = l1i*yr[3] - l1r*yi[3];   // v13
    v[12] = l0r*yr[3] + l0i*yi[3];  v[13] = l0i*yr[3] - l0r*yi[3];   // v03
    v[14] = l1r*yr[2] + l1i*yi[2];  v[15] = l1i*yr[2] - l1r*yi[2];   // v12
}

// ---------------------------------------------------------------------------
// Warp-local prefetchers (cp.async)
__device__ __forceinline__ void stage_xs(uint32_t sb, int wid, int lid,
                                         const float* __restrict__ bins_re,
                                         const float* __restrict__ bins_im,
                                         int b, int t0, int f0)
{
    #pragma unroll
    for (int rr = 0; rr < 8; rr++) {
        const int ch = rr >> 1, im = rr & 1;
        const float* src = (im ? bins_im : bins_re)
                         + ((size_t)((b * TT + t0 + wid) * 4 + ch)) * FF;
        const uint32_t drow = sb + OFF_XS + (wid * 8 + rr) * 272;
        #pragma unroll
        for (int j0 = 0; j0 < 96; j0 += 32) {
            const int j = j0 + lid;
            if (j < 66) {
                int gf = f0 - 1 + j;
                gf = gf < 0 ? 0 : (gf > FF - 1 ? FF - 1 : gf);
                CP4(drow + j * 4, src + gf);
            }
        }
    }
}

__device__ __forceinline__ void stage_b(uint32_t sb, int wid, int lid,
                                        uint32_t offH, uint32_t offL, int f0)
{
    #pragma unroll
    for (int it0 = 0; it0 < 96; it0 += 32) {
        const int it = it0 + lid;
        const int row = wid * 12 + (it >> 3), q = it & 7;
        const uint32_t dh = sb + offH + row * 144 + q * 16;
        const uint32_t dl = sb + offL + row * 144 + q * 16;
        CP16(dh, g_Bh + row * KPAD + f0 + q * 8);
        CP16(dl, g_Bl + row * KPAD + f0 + q * 8);
    }
}

// ---------------------------------------------------------------------------
__global__ __launch_bounds__(NTH, 2)
void pv_main(const float* __restrict__ bins_re, const float* __restrict__ bins_im,
             const float* __restrict__ c2pv_re, const float* __restrict__ c2pv_im,
             float* __restrict__ out)
{
    extern __shared__ unsigned char smem[];
    float* smf = (float*)smem;
    const uint32_t sb = smem_u32(smem);
    const int tid = threadIdx.x;
    const int wid = tid >> 5;
    const int lid = tid & 31;
    const int b   = blockIdx.y;
    const int t0  = blockIdx.x * FPC;

    float* c2s = smf + OFF_C2 / 4;
    for (int i = tid; i < 256; i += NTH) {
        c2s[i] = c2pv_re[i]; c2s[256 + i] = c2pv_im[i];
    }

    float* xs = smf + OFF_XS / 4;   // [64 rows][68]; row = wid*8 + ch*2 + im

    // prologue: stage chunk 0 (xs + B buf0)
    stage_xs(sb, wid, lid, bins_re, bins_im, b, t0, 0);
    stage_b(sb, wid, lid, OFF_B0H, OFF_B0L, 0);
    CP_COMMIT();

    // ldmatrix lane address components (fixed per thread)
    const int rowA  = wid * 16 + (lid & 7) + ((lid >> 3) & 1) * 8;
    const int koffA = (lid >> 4) * 8;
    const int nB    = (lid & 7) + ((lid >> 4) << 3);
    const int kB    = ((lid >> 3) & 1) * 8;

    float acc[12][4];
    #pragma unroll
    for (int nb = 0; nb < 12; nb++) {
        acc[nb][0] = 0.f; acc[nb][1] = 0.f; acc[nb][2] = 0.f; acc[nb][3] = 0.f;
    }

    for (int chunk = 0; chunk < NCHUNK; chunk++) {
        const int f0 = chunk * KC;
        CP_WAIT0();
        __syncthreads();           // xs(chunk) + Bbuf[chunk&1] visible to all

        // ---- Phase A (warp-local: frame `wid`, rows 16*wid..16*wid+15) ----
        const float* xb = xs + wid * 8 * 68;
        const int fl = lid * 2;
        float v0[16], v1[16];
        {
            const int f = f0 + fl;
            if (f < FF) {
                const int fm = (f - 1 < 0) ? 0 : ((f - 1 > FF - 3) ? FF - 3 : f - 1);
                phaseA_f(xb, f - f0 + 1, fm - f0 + 1, fm - f0 + 3, v0);
            } else {
                for (int c = 0; c < 16; c++) v0[c] = 0.f;
            }
        }
        {
            const int f = f0 + fl + 1;
            if (f < FF) {
                const int fm = (f - 1 > FF - 3) ? FF - 3 : f - 1;
                phaseA_f(xb, f - f0 + 1, fm - f0 + 1, fm - f0 + 3, v1);
            } else {
                for (int c = 0; c < 16; c++) v1[c] = 0.f;
            }
        }
        #pragma unroll
        for (int c = 0; c < 16; c++) {
            const int row = wid * 16 + c;
            __nv_bfloat162 h;
            h.x = __float2bfloat16(v0[c]); h.y = __float2bfloat16(v1[c]);
            *(__nv_bfloat162*)(smem + OFF_AH + row * 144 + fl * 2) = h;
            __nv_bfloat162 l;
            l.x = __float2bfloat16(v0[c] - __bfloat162float(h.x));
            l.y = __float2bfloat16(v1[c] - __bfloat162float(h.y));
            *(__nv_bfloat162*)(smem + OFF_AL + row * 144 + fl * 2) = l;
        }
        __syncwarp();              // A rows of this warp visible to itself

        // ---- prefetch next chunk (overlaps the MMA below) ----
        if (chunk + 1 < NCHUNK) {
            const int f0n = f0 + KC;
            stage_xs(sb, wid, lid, bins_re, bins_im, b, t0, f0n);
            if ((chunk + 1) & 1) stage_b(sb, wid, lid, OFF_B1H, OFF_B1L, f0n);
            else                 stage_b(sb, wid, lid, OFF_B0H, OFF_B0L, f0n);
        }
        CP_COMMIT();

        // ---- MMA: 4 k-steps x 12 n-blocks x 3 split-products ----
        const uint32_t offBH = (chunk & 1) ? OFF_B1H : OFF_B0H;
        #pragma unroll
        for (int ks = 0; ks < 4; ks++) {
            const int k0 = ks * 16;
            const uint32_t aA = sb + OFF_AH + rowA * 144 + (k0 + koffA) * 2;
            uint32_t ah[4], al[4];
            LDSM4(ah, aA);
            LDSM4(al, aA + (OFF_AL - OFF_AH));
            #pragma unroll
            for (int nbp = 0; nbp < 6; nbp++) {
                const uint32_t aB = sb + offBH + (nbp * 16 + nB) * 144 + (k0 + kB) * 2;
                uint32_t bh[4], bl[4];
                LDSM4(bh, aB);
                LDSM4(bl, aB + (OFF_B0L - OFF_B0H));
                MMA16816(acc[2*nbp],     ah, bh[0], bh[1]);
                MMA16816(acc[2*nbp],     al, bh[0], bh[1]);
                MMA16816(acc[2*nbp],     ah, bl[0], bl[1]);
                MMA16816(acc[2*nbp + 1], ah, bh[2], bh[3]);
                MMA16816(acc[2*nbp + 1], al, bh[2], bh[3]);
                MMA16816(acc[2*nbp + 1], ah, bl[2], bl[3]);
            }
        }
    }
    __syncthreads();

    // accumulators -> Dsm [128 m][97 stride]
    float* Dsm = smf + OFF_DSM / 4;
    {
        const int m0 = wid * 16 + (lid >> 2);
        const int ncol = (lid & 3) * 2;
        #pragma unroll
        for (int nb = 0; nb < 12; nb++) {
            const int n0 = nb * 8 + ncol;
            Dsm[m0 * 97 + n0]           = acc[nb][0];
            Dsm[m0 * 97 + n0 + 1]       = acc[nb][1];
            Dsm[(m0 + 8) * 97 + n0]     = acc[nb][2];
            Dsm[(m0 + 8) * 97 + n0 + 1] = acc[nb][3];
        }
    }
    __syncthreads();

    // Epilogue: reconstruct Hermitian bc, project with c2pv, scale, store
    if (tid < 192) {
        const int k = tid % KK, g = tid / KK, p0 = g * 4;
        const float invd = g_invds[k];
        for (int fr = 0; fr < FPC; fr++) {
            float sr[16], si[16];
            #pragma unroll
            for (int c = 0; c < 16; c++) {
                sr[c] = Dsm[(fr * 16 + c) * 97 + k];
                si[c] = Dsm[(fr * 16 + c) * 97 + 48 + k];
            }
            float br[16], bi[16];
            br[0]=sr[0];  bi[0]=si[0];   br[5]=sr[1];   bi[5]=si[1];
            br[10]=sr[4]; bi[10]=si[4];  br[15]=sr[5];  bi[15]=si[5];
            br[1]=sr[2]-si[3];    bi[1]=si[2]+sr[3];
            br[4]=sr[2]+si[3];    bi[4]=si[2]-sr[3];
            br[11]=sr[6]-si[7];   bi[11]=si[6]+sr[7];
            br[14]=sr[6]+si[7];   bi[14]=si[6]-sr[7];
            br[2]=sr[8]-si[9];    bi[2]=si[8]+sr[9];
            br[8]=sr[8]+si[9];    bi[8]=si[8]-sr[9];
            br[7]=sr[10]-si[11];  bi[7]=si[10]+sr[11];
            br[13]=sr[10]+si[11]; bi[13]=si[10]-sr[11];
            br[3]=sr[12]-si[13];  bi[3]=si[12]+sr[13];
            br[12]=sr[12]+si[13]; bi[12]=si[12]-sr[13];
            br[6]=sr[14]-si[15];  bi[6]=si[14]+sr[15];
            br[9]=sr[14]+si[15];  bi[9]=si[14]-sr[15];
            float a0=0.f, a1=0.f, a2=0.f, a3=0.f;
            #pragma unroll
            for (int c = 0; c < 16; c++) {
                const float vr = br[c], vi = bi[c];
                a0 = fmaf(c2s[(p0+0)*16+c], vr, a0); a0 = fmaf(-c2s[256+(p0+0)*16+c], vi, a0);
                a1 = fmaf(c2s[(p0+1)*16+c], vr, a1); a1 = fmaf(-c2s[256+(p0+1)*16+c], vi, a1);
                a2 = fmaf(c2s[(p0+2)*16+c], vr, a2); a2 = fmaf(-c2s[256+(p0+2)*16+c], vi, a2);
                a3 = fmaf(c2s[(p0+3)*16+c], vr, a3); a3 = fmaf(-c2s[256+(p0+3)*16+c], vi, a3);
            }
            float4 o = make_float4(a0*invd, a1*invd, a2*invd, a3*invd);
            *(float4*)(out + (((size_t)(b * KK + k)) * TT + (t0 + fr)) * 16 + p0) = o;
        }
    }
}

// ---------------------------------------------------------------------------
// IIR: chunked parallel scan, in-place on out (B,K,T,16). Real IIR commutes
// with the real-linear c2pv projection, so smoothing projected values is exact.
__global__ __launch_bounds__(256)
void pv_iir(float* __restrict__ out, const float* __restrict__ tau)
{
    __shared__ float Lend[256];
    __shared__ float Cin[256];
    const int chain = blockIdx.x;
    const int k = chain % KK;
    const int p = threadIdx.x & 15;
    const int c = threadIdx.x >> 4;
    const float a = expf(-10.0f / tau[k]);
    const float bco = 1.0f - a;
    float* base = out + (size_t)chain * (TT * 16) + (size_t)c * 64 * 16 + p;

    float v[64];
    #pragma unroll
    for (int i = 0; i < 64; i++) v[i] = base[i * 16];
    float y = (c == 0) ? v[0] : bco * v[0];
    v[0] = y;
    #pragma unroll
    for (int i = 1; i < 64; i++) { y = fmaf(a, y, bco * v[i]); v[i] = y; }

    float A = a;
    #pragma unroll
    for (int s = 0; s < 6; s++) A *= A;           // a^64

    Lend[c * 16 + p] = y;
    __syncthreads();
    if (threadIdx.x < 16) {
        float carry = 0.f;
        #pragma unroll
        for (int cc = 0; cc < 16; cc++) {
            Cin[cc * 16 + threadIdx.x] = carry;
            carry = Lend[cc * 16 + threadIdx.x] + A * carry;
        }
    }
    __syncthreads();
    const float carry = Cin[c * 16 + p];
    float pw = a;
    #pragma unroll
    for (int i = 0; i < 64; i++) { base[i * 16] = v[i] + pw * carry; pw *= a; }
}

// ---------------------------------------------------------------------------
extern "C" void kernel_launch(void* const* d_in, const int* in_sizes, int n_in,
                              void* d_out, int out_size)
{
    const float* bins_re = (const float*)d_in[0];
    const float* bins_im = (const float*)d_in[1];
    const float* band_re = (const float*)d_in[2];
    const float* band_im = (const float*)d_in[3];
    const float* c2pv_re = (const float*)d_in[4];
    const float* c2pv_im = (const float*)d_in[5];
    const float* tau     = (const float*)d_in[6];
    float* out = (float*)d_out;

    cudaFuncSetAttribute(pv_main, cudaFuncAttributeMaxDynamicSharedMemorySize,
                         SMEM_BYTES);

    pv_prep_b<<<(96 * KPAD + 255) / 256, 256>>>(band_re, band_im);
    pv_invds<<<KK, 128>>>(band_re);

    dim3 grid(TT / FPC, BB);
    pv_main<<<grid, NTH, SMEM_BYTES>>>(bins_re, bins_im, c2pv_re, c2pv_im, out);

    pv_iir<<<BB * KK, 256>>>(out, tau);
}

// round 12
// speedup vs baseline: 6.8336x; 1.1144x over previous
#include <cuda_runtime.h>
#include <cuda_bf16.h>
#include <cstdint>

#define FF 481
#define KK 48
#define TT 1024
#define BB 4
#define FPC 8            // frames per CTA (8 warps; Phase A: warp <-> frame)
#define NTH 256
#define KC 64            // f per chunk
#define NCHUNK 8
#define KPAD 512         // 8 * 64

// smem byte offsets. A/B tiles row stride 72 bf16 = 144 B (ldmatrix conflict-free).
#define OFF_AH   0               // 128 x 72 bf16 = 18432
#define OFF_AL   18432
#define OFF_B0H  36864           // 96 x 72 bf16 = 13824
#define OFF_B0L  50688
#define OFF_B1H  64512
#define OFF_B1L  78336
#define OFF_C2   92160           // 512 floats = 2048
#define SMEM_BYTES 94208
#define OFF_DSM  0               // epilogue alias: 128*97 floats = 49664 B

__device__ float g_invds[KK];
__device__ __align__(16) __nv_bfloat16 g_Bh[96 * KPAD];
__device__ __align__(16) __nv_bfloat16 g_Bl[96 * KPAD];

// ---------------------------------------------------------------------------
__device__ __forceinline__ float frsqrt_a(float x) {
    float r; asm("rsqrt.approx.f32 %0, %1;" : "=f"(r) : "f"(x)); return r;
}
__device__ __forceinline__ float frcp_a(float x) {
    float r; asm("rcp.approx.f32 %0, %1;" : "=f"(r) : "f"(x)); return r;
}
__device__ __forceinline__ uint32_t smem_u32(const void* p) {
    uint32_t a;
    asm("{ .reg .u64 t; cvta.to.shared.u64 t, %1; cvt.u32.u64 %0, t; }" : "=r"(a) : "l"(p));
    return a;
}

#define CP16(dst, src) asm volatile("cp.async.cg.shared.global [%0], [%1], 16;" :: "r"(dst), "l"(src))
#define CP_COMMIT()    asm volatile("cp.async.commit_group;" ::: "memory")
#define CP_WAIT0()     asm volatile("cp.async.wait_group 0;" ::: "memory")

#define LDSM4(r, a)                                                          \
    asm volatile("ldmatrix.sync.aligned.m8n8.x4.shared.b16 {%0,%1,%2,%3}, [%4];" \
        : "=r"((r)[0]), "=r"((r)[1]), "=r"((r)[2]), "=r"((r)[3]) : "r"(a))

#define MMA16816(c, a, b0, b1)                                               \
    asm volatile("mma.sync.aligned.m16n8k16.row.col.f32.bf16.bf16.f32 "      \
        "{%0,%1,%2,%3}, {%4,%5,%6,%7}, {%8,%9}, {%0,%1,%2,%3};"              \
        : "+f"((c)[0]), "+f"((c)[1]), "+f"((c)[2]), "+f"((c)[3])             \
        : "r"((a)[0]), "r"((a)[1]), "r"((a)[2]), "r"((a)[3]),                \
          "r"(b0), "r"(b1))

// ---------------------------------------------------------------------------
// Prep (merged): blocks [0,192): band -> bf16 hi/lo [96 n][KPAD];
// blocks [192,240): invds[k] = 1 / sum_f band_re[f,k].
__global__ void pv_prep(const float* __restrict__ band_re,
                        const float* __restrict__ band_im)
{
    if (blockIdx.x < 192) {
        const int idx = blockIdx.x * 256 + threadIdx.x;   // < 96*512
        const int n = idx >> 9, f = idx & (KPAD - 1);
        float v = 0.f;
        if (f < FF) v = (n < KK) ? band_re[f * KK + n] : band_im[f * KK + (n - KK)];
        const __nv_bfloat16 h = __float2bfloat16(v);
        g_Bh[idx] = h;
        g_Bl[idx] = __float2bfloat16(v - __bfloat162float(h));
    } else {
        const int k = blockIdx.x - 192;
        float s = 0.f;
        for (int f = threadIdx.x; f < FF; f += 256) s += band_re[f * KK + k];
        __shared__ float red[8];
        #pragma unroll
        for (int o = 16; o; o >>= 1) s += __shfl_xor_sync(0xffffffffu, s, o);
        if ((threadIdx.x & 31) == 0) red[threadIdx.x >> 5] = s;
        __syncthreads();
        if (threadIdx.x == 0) {
            float t = 0.f;
            #pragma unroll
            for (int i = 0; i < 8; i++) t += red[i];
            g_invds[k] = 1.0f / fmaxf(t, 1e-20f);
        }
    }
}

// ---------------------------------------------------------------------------
// Phase A per frequency, direct from global (L1-resident window).
__device__ __forceinline__ void phaseA_g(const float* __restrict__ re,
                                         const float* __restrict__ im,
                                         int f, float* v)
{
    int fm = f - 1; fm = fm < 0 ? 0 : (fm > FF - 3 ? FF - 3 : fm);
    const int fp = fm + 2;
    float yr[4], yi[4], dv[4];
    float dsum = 0.f;
    #pragma unroll
    for (int ch = 0; ch < 4; ch++) {
        const float* rr = re + ch * FF;
        const float* ii = im + ch * FF;
        const float xr = __ldg(rr + f),  xi = __ldg(ii + f);
        const float mr = __ldg(rr + fm), mi = __ldg(ii + fm);
        const float pr = __ldg(rr + fp), pi = __ldg(ii + fp);
        const float d  = xr * xr + xi * xi;
        const float dm = mr * mr + mi * mi;
        const float dp = pr * pr + pi * pi;
        const float ur = mr * pr + mi * pi;       // conj(x_fm) * x_fp
        const float ui = mr * pi - mi * pr;
        const float s  = d * frsqrt_a(fmaxf(d * dm * dp, 1e-38f)); // = |x_f|/|u|
        yr[ch] = s * ur; yi[ch] = s * ui;
        dv[ch] = d; dsum += d;
    }
    const float invp = frcp_a(fmaxf(dsum, 1e-20f));
    const float l0r = yr[0] * invp, l0i = yi[0] * invp;
    const float l1r = yr[1] * invp, l1i = yi[1] * invp;
    const float l2r = yr[2] * invp, l2i = yi[2] * invp;
    v[0]  = dv[0] * invp;  v[1]  = dv[1] * invp;
    v[2]  = l0r*yr[1] + l0i*yi[1];  v[3]  = l0i*yr[1] - l0r*yi[1];   // v01
    v[4]  = dv[2] * invp;  v[5]  = dv[3] * invp;
    v[6]  = l2r*yr[3] + l2i*yi[3];  v[7]  = l2i*yr[3] - l2r*yi[3];   // v23
    v[8]  = l0r*yr[2] + l0i*yi[2];  v[9]  = l0i*yr[2] - l0r*yi[2];   // v02
    v[10] = l1r*yr[3] + l1i*yi[3];  v[11] = l1i*yr[3] - l1r*yi[3];   // v13
    v[12] = l0r*yr[3] + l0i*yi[3];  v[13] = l0i*yr[3] - l0r*yi[3];   // v03
    v[14] = l1r*yr[2] + l1i*yi[2];  v[15] = l1i*yr[2] - l1r*yi[2];   // v12
}

// B tile prefetcher (warp-cooperative, cp.async 16B)
__device__ __forceinline__ void stage_b(uint32_t sb, int wid, int lid,
                                        uint32_t offH, uint32_t offL, int f0)
{
    #pragma unroll
    for (int it0 = 0; it0 < 96; it0 += 32) {
        const int it = it0 + lid;
        const int row = wid * 12 + (it >> 3), q = it & 7;
        CP16(sb + offH + row * 144 + q * 16, g_Bh + row * KPAD + f0 + q * 8);
        CP16(sb + offL + row * 144 + q * 16, g_Bl + row * KPAD + f0 + q * 8);
    }
}

// ---------------------------------------------------------------------------
__global__ __launch_bounds__(NTH, 2)
void pv_main(const float* __restrict__ bins_re, const float* __restrict__ bins_im,
             const float* __restrict__ c2pv_re, const float* __restrict__ c2pv_im,
             float* __restrict__ out)
{
    extern __shared__ unsigned char smem[];
    float* smf = (float*)smem;
    const uint32_t sb = smem_u32(smem);
    const int tid = threadIdx.x;
    const int wid = tid >> 5;
    const int lid = tid & 31;
    const int b   = blockIdx.y;
    const int t0  = blockIdx.x * FPC;

    float* c2s = smf + OFF_C2 / 4;
    for (int i = tid; i < 256; i += NTH) {
        c2s[i] = c2pv_re[i]; c2s[256 + i] = c2pv_im[i];
    }

    // prologue: stage B chunk 0
    stage_b(sb, wid, lid, OFF_B0H, OFF_B0L, 0);
    CP_COMMIT();

    // Phase A source rows for this warp's frame
    const float* reB = bins_re + ((size_t)((b * TT + t0 + wid) * 4)) * FF;
    const float* imB = bins_im + ((size_t)((b * TT + t0 + wid) * 4)) * FF;

    // MMA tile assignment: m-block (32 rows) = wid&3, n-half (48 cols) = wid>>2
    const int mBase = (wid & 3) * 32;
    const int nBase = (wid >> 2) * 48;
    const int rA    = (lid & 7) + ((lid >> 3) & 1) * 8;   // row within 16
    const int koffA = (lid >> 4) * 8;
    const int nB    = (lid & 7) + ((lid >> 4) << 3);
    const int kB    = ((lid >> 3) & 1) * 8;

    float acc[2][6][4];
    #pragma unroll
    for (int mt = 0; mt < 2; mt++)
        #pragma unroll
        for (int nb = 0; nb < 6; nb++) {
            acc[mt][nb][0] = 0.f; acc[mt][nb][1] = 0.f;
            acc[mt][nb][2] = 0.f; acc[mt][nb][3] = 0.f;
        }

    for (int chunk = 0; chunk < NCHUNK; chunk++) {
        const int f0 = chunk * KC;
        CP_WAIT0();
        __syncthreads();           // B buf ready; prev MMA done (A safe to overwrite)

        // ---- Phase A: frame `wid`, f-pair (f0+2*lid, +1) -> A rows 16*wid.. ----
        const int fl = lid * 2;
        float v0[16], v1[16];
        {
            const int f = f0 + fl;
            if (f < FF) phaseA_g(reB, imB, f, v0);
            else        for (int c = 0; c < 16; c++) v0[c] = 0.f;
        }
        {
            const int f = f0 + fl + 1;
            if (f < FF) phaseA_g(reB, imB, f, v1);
            else        for (int c = 0; c < 16; c++) v1[c] = 0.f;
        }
        #pragma unroll
        for (int c = 0; c < 16; c++) {
            const int row = wid * 16 + c;
            __nv_bfloat162 h;
            h.x = __float2bfloat16(v0[c]); h.y = __float2bfloat16(v1[c]);
            *(__nv_bfloat162*)(smem + OFF_AH + row * 144 + fl * 2) = h;
            __nv_bfloat162 l;
            l.x = __float2bfloat16(v0[c] - __bfloat162float(h.x));
            l.y = __float2bfloat16(v1[c] - __bfloat162float(h.y));
            *(__nv_bfloat162*)(smem + OFF_AL + row * 144 + fl * 2) = l;
        }
        __syncthreads();           // all warps' A visible (cross-warp MMA tiles)

        // ---- prefetch next B (overlaps MMA below) ----
        if (chunk + 1 < NCHUNK) {
            const int f0n = f0 + KC;
            if ((chunk + 1) & 1) stage_b(sb, wid, lid, OFF_B1H, OFF_B1L, f0n);
            else                 stage_b(sb, wid, lid, OFF_B0H, OFF_B0L, f0n);
        }
        CP_COMMIT();

        // ---- MMA: warp tile 32(m) x 48(n); 4 ks x 3 nbp x 2 mt x 3 products ----
        const uint32_t offBH = (chunk & 1) ? OFF_B1H : OFF_B0H;
        #pragma unroll
        for (int ks = 0; ks < 4; ks++) {
            const int k0 = ks * 16;
            uint32_t ah[2][4], al[2][4];
            #pragma unroll
            for (int mt = 0; mt < 2; mt++) {
                const uint32_t aA = sb + OFF_AH
                    + (mBase + mt * 16 + rA) * 144 + (k0 + koffA) * 2;
                LDSM4(ah[mt], aA);
                LDSM4(al[mt], aA + (OFF_AL - OFF_AH));
            }
            #pragma unroll
            for (int nbp = 0; nbp < 3; nbp++) {
                const uint32_t aB = sb + offBH
                    + (nBase + nbp * 16 + nB) * 144 + (k0 + kB) * 2;
                uint32_t bh[4], bl[4];
                LDSM4(bh, aB);
                LDSM4(bl, aB + (OFF_B0L - OFF_B0H));
                #pragma unroll
                for (int mt = 0; mt < 2; mt++) {
                    MMA16816(acc[mt][2*nbp],     ah[mt], bh[0], bh[1]);
                    MMA16816(acc[mt][2*nbp],     al[mt], bh[0], bh[1]);
                    MMA16816(acc[mt][2*nbp],     ah[mt], bl[0], bl[1]);
                    MMA16816(acc[mt][2*nbp + 1], ah[mt], bh[2], bh[3]);
                    MMA16816(acc[mt][2*nbp + 1], al[mt], bh[2], bh[3]);
                    MMA16816(acc[mt][2*nbp + 1], ah[mt], bl[2], bl[3]);
                }
            }
        }
    }
    __syncthreads();

    // accumulators -> Dsm [128 m][97 stride] (aliases A tiles)
    float* Dsm = smf + OFF_DSM / 4;
    {
        const int ncol = (lid & 3) * 2;
        #pragma unroll
        for (int mt = 0; mt < 2; mt++) {
            const int m0 = mBase + mt * 16 + (lid >> 2);
            #pragma unroll
            for (int nb = 0; nb < 6; nb++) {
                const int n0 = nBase + nb * 8 + ncol;
                Dsm[m0 * 97 + n0]           = acc[mt][nb][0];
                Dsm[m0 * 97 + n0 + 1]       = acc[mt][nb][1];
                Dsm[(m0 + 8) * 97 + n0]     = acc[mt][nb][2];
                Dsm[(m0 + 8) * 97 + n0 + 1] = acc[mt][nb][3];
            }
        }
    }
    __syncthreads();

    // Epilogue: reconstruct Hermitian bc, project with c2pv, scale, store
    if (tid < 192) {
        const int k = tid % KK, g = tid / KK, p0 = g * 4;
        const float invd = g_invds[k];
        for (int fr = 0; fr < FPC; fr++) {
            float sr[16], si[16];
            #pragma unroll
            for (int c = 0; c < 16; c++) {
                sr[c] = Dsm[(fr * 16 + c) * 97 + k];
                si[c] = Dsm[(fr * 16 + c) * 97 + 48 + k];
            }
            float br[16], bi[16];
            br[0]=sr[0];  bi[0]=si[0];   br[5]=sr[1];   bi[5]=si[1];
            br[10]=sr[4]; bi[10]=si[4];  br[15]=sr[5];  bi[15]=si[5];
            br[1]=sr[2]-si[3];    bi[1]=si[2]+sr[3];
            br[4]=sr[2]+si[3];    bi[4]=si[2]-sr[3];
            br[11]=sr[6]-si[7];   bi[11]=si[6]+sr[7];
            br[14]=sr[6]+si[7];   bi[14]=si[6]-sr[7];
            br[2]=sr[8]-si[9];    bi[2]=si[8]+sr[9];
            br[8]=sr[8]+si[9];    bi[8]=si[8]-sr[9];
            br[7]=sr[10]-si[11];  bi[7]=si[10]+sr[11];
            br[13]=sr[10]+si[11]; bi[13]=si[10]-sr[11];
            br[3]=sr[12]-si[13];  bi[3]=si[12]+sr[13];
            br[12]=sr[12]+si[13]; bi[12]=si[12]-sr[13];
            br[6]=sr[14]-si[15];  bi[6]=si[14]+sr[15];
            br[9]=sr[14]+si[15];  bi[9]=si[14]-sr[15];
            float a0=0.f, a1=0.f, a2=0.f, a3=0.f;
            #pragma unroll
            for (int c = 0; c < 16; c++) {
                const float vr = br[c], vi = bi[c];
                a0 = fmaf(c2s[(p0+0)*16+c], vr, a0); a0 = fmaf(-c2s[256+(p0+0)*16+c], vi, a0);
                a1 = fmaf(c2s[(p0+1)*16+c], vr, a1); a1 = fmaf(-c2s[256+(p0+1)*16+c], vi, a1);
                a2 = fmaf(c2s[(p0+2)*16+c], vr, a2); a2 = fmaf(-c2s[256+(p0+2)*16+c], vi, a2);
                a3 = fmaf(c2s[(p0+3)*16+c], vr, a3); a3 = fmaf(-c2s[256+(p0+3)*16+c], vi, a3);
            }
            float4 o = make_float4(a0*invd, a1*invd, a2*invd, a3*invd);
            *(float4*)(out + (((size_t)(b * KK + k)) * TT + (t0 + fr)) * 16 + p0) = o;
        }
    }
}

// ---------------------------------------------------------------------------
// IIR: 32 chunks of 32 frames, chunked parallel scan, in-place on out (B,K,T,16).
__global__ __launch_bounds__(512)
void pv_iir(float* __restrict__ out, const float* __restrict__ tau)
{
    __shared__ float Lend[512];
    __shared__ float Cin[512];
    const int chain = blockIdx.x;          // b*KK + k
    const int k = chain % KK;
    const int p = threadIdx.x & 15;
    const int c = threadIdx.x >> 4;        // chunk 0..31
    const float a = expf(-10.0f / tau[k]);
    const float bco = 1.0f - a;
    float* base = out + (size_t)chain * (TT * 16) + (size_t)c * 32 * 16 + p;

    float v[32];
    #pragma unroll
    for (int i = 0; i < 32; i++) v[i] = base[i * 16];
    float y = (c == 0) ? v[0] : bco * v[0];
    v[0] = y;
    #pragma unroll
    for (int i = 1; i < 32; i++) { y = fmaf(a, y, bco * v[i]); v[i] = y; }

    float A = a;
    #pragma unroll
    for (int s = 0; s < 5; s++) A *= A;    // a^32

    Lend[c * 16 + p] = y;
    __syncthreads();
    if (threadIdx.x < 16) {                 // one thread per p: serial over chunks
        float carry = 0.f;
        #pragma unroll
        for (int cc = 0; cc < 32; cc++) {
            Cin[cc * 16 + threadIdx.x] = carry;
            carry = Lend[cc * 16 + threadIdx.x] + A * carry;
        }
    }
    __syncthreads();
    const float carry = Cin[c * 16 + p];
    float pw = a;
    #pragma unroll
    for (int i = 0; i < 32; i++) { base[i * 16] = v[i] + pw * carry; pw *= a; }
}

// ---------------------------------------------------------------------------
extern "C" void kernel_launch(void* const* d_in, const int* in_sizes, int n_in,
                              void* d_out, int out_size)
{
    const float* bins_re = (const float*)d_in[0];
    const float* bins_im = (const float*)d_in[1];
    const float* band_re = (const float*)d_in[2];
    const float* band_im = (const float*)d_in[3];
    const float* c2pv_re = (const float*)d_in[4];
    const float* c2pv_im = (const float*)d_in[5];
    const float* tau     = (const float*)d_in[6];
    float* out = (float*)d_out;

    cudaFuncSetAttribute(pv_main, cudaFuncAttributeMaxDynamicSharedMemorySize,
                         SMEM_BYTES);

    pv_prep<<<240, 256>>>(band_re, band_im);

    dim3 grid(TT / FPC, BB);
    pv_main<<<grid, NTH, SMEM_BYTES>>>(bins_re, bins_im, c2pv_re, c2pv_im, out);

    pv_iir<<<BB * KK, 512>>>(out, tau);
}